// round 17
// baseline (speedup 1.0000x reference)
#include <cuda_runtime.h>
#include <cuda_bf16.h>

// Problem shape (fixed for this bench problem)
#define SEQ  1024
#define BAT  512
#define NTAG 64
#define TSTRIDE (BAT * NTAG)
#define LN2 0.69314718055994531f
#define SE_STR 80          // 16 cols | gap 16 | 16 cols layout, conflict-free

typedef unsigned long long ull;

// Scratch (device globals). Zero at load; finishers restore zero each call.
__device__ float g_score[BAT];
__device__ float g_v[BAT][NTAG];
__device__ float g_u[BAT][NTAG];
__device__ float g_m0[BAT];
__device__ int   g_esF[BAT];
__device__ int   g_esB[BAT];
__device__ float g_denomG[BAT];
__device__ int   g_tick[BAT];
__device__ ull   g_acc;
__device__ int   g_done;
__device__ int   g_mask_zero;
__device__ int   g_maskT[BAT * SEQ];

__device__ __forceinline__ int load_tag(const void* tags, size_t idx, int is64) {
    if (is64) return (int)((const long long*)tags)[idx];
    return ((const int*)tags)[idx];
}

// ---------------------------------------------------------------------------
__global__ void mask_transpose_kernel(const int* __restrict__ mask) {
    int idx = blockIdx.x * blockDim.x + threadIdx.x;
    if (idx < SEQ * BAT) {
        int t = idx / BAT;
        int b = idx - t * BAT;
        int v = mask[idx];
        g_maskT[b * SEQ + t] = v;
        if (v != 1) g_mask_zero = 1;
    }
}

#define FMA2(acc, s, e) \
    asm("fma.rn.f32x2 %0, %1, %2, %0;" : "+l"(acc) : "l"(s), "l"(e))
#define ADD2(a, b) \
    asm("add.rn.f32x2 %0, %0, %1;" : "+l"(a) : "l"(b))

// ---------------------------------------------------------------------------
// Row-split dual-column half dot: this thread's 32 rows for columns (k, k+32).
// 8 LDS.128 (two disjoint-bank broadcast groups per warp) + 32 FFMA2.
// ---------------------------------------------------------------------------
__device__ __forceinline__ void dot_rs(
    const float* __restrict__ rdh,
    const ull* __restrict__ EpA, const ull* __restrict__ EpB,
    float& pA, float& pB)
{
    const ulonglong2* s2 = (const ulonglong2*)rdh;
    ull aA0 = 0ull, aA1 = 0ull, aB0 = 0ull, aB1 = 0ull;
#pragma unroll
    for (int i = 0; i < 8; i++) {
        ulonglong2 q = s2[i];
        FMA2(aA0, q.x, EpA[2 * i + 0]);
        FMA2(aB0, q.x, EpB[2 * i + 0]);
        FMA2(aA1, q.y, EpA[2 * i + 1]);
        FMA2(aB1, q.y, EpB[2 * i + 1]);
    }
    ADD2(aA0, aA1);
    ADD2(aB0, aB1);
    float l0, h0, l1, h1;
    asm("mov.b64 {%0, %1}, %2;" : "=f"(l0), "=f"(h0) : "l"(aA0));
    asm("mov.b64 {%0, %1}, %2;" : "=f"(l1), "=f"(h1) : "l"(aB0));
    pA = l0 + h0;
    pB = l1 + h1;
}

// 64-wide single-column dot (general path only; champion form)
__device__ __forceinline__ float dot64(const float* __restrict__ rd,
                                       const ull* __restrict__ Ep)
{
    const ulonglong2* s2 = (const ulonglong2*)rd;
    ull a0 = 0ull, a1 = 0ull, a2 = 0ull, a3 = 0ull;
#pragma unroll
    for (int i = 0; i < 16; i += 2) {
        ulonglong2 qA = s2[i];
        ulonglong2 qB = s2[i + 1];
        FMA2(a0, qA.x, Ep[2 * i + 0]);
        FMA2(a1, qA.y, Ep[2 * i + 1]);
        FMA2(a2, qB.x, Ep[2 * i + 2]);
        FMA2(a3, qB.y, Ep[2 * i + 3]);
    }
    ADD2(a0, a2);
    ADD2(a1, a3);
    ADD2(a0, a1);
    float lo, hi;
    asm("mov.b64 {%0, %1}, %2;" : "=f"(lo), "=f"(hi) : "l"(a0));
    return lo + hi;
}

// ---------------------------------------------------------------------------
// Forward step, row-split. Double-buffered (read rd, write wr), ONE sync.
// own/ship/recv pair exchange via shfl_xor (R8-proven topology).
// ---------------------------------------------------------------------------
template <bool RN>
__device__ __forceinline__ float fstep_rs(
    const float* __restrict__ rd, float* __restrict__ wr,
    int pos, int hoff, int h,
    const ull* __restrict__ EpA, const ull* __restrict__ EpB,
    float rawv, int& e_sum)
{
    const float c = __expf(rawv);
    float cmul = c;
    if (RN) {
        const float s0 = rd[0];
        int ex = (__float_as_int(s0) >> 23) & 0xFF;
        ex = max(1, min(ex, 253));
        e_sum += ex - 127;
        cmul = c * __int_as_float((254 - ex) << 23);
    }
    float pA, pB;
    dot_rs(rd + hoff, EpA, EpB, pA, pB);
    const float own  = h ? pB : pA;   // my final column's partial (my rows)
    const float ship = h ? pA : pB;   // what my pair partner needs
    const float recv = __shfl_xor_sync(0xffffffffu, ship, 1);
    const float snew = (own + recv) * cmul;
    wr[pos] = snew;
    __syncthreads();
    return snew;
}

// ---------------------------------------------------------------------------
// Backward step, row-split: u_new_j = sum_i E[j][i] * (u_i * c_i).
// Alternating buffer (write w, sync, dot) — champion protocol.
// ---------------------------------------------------------------------------
template <bool RN>
__device__ __forceinline__ float bstep_rs(
    float* __restrict__ buf,
    int pos, int hoff, int h,
    const ull* __restrict__ EpA, const ull* __restrict__ EpB,
    float rawv, float u, int& e_sum)
{
    buf[pos] = u * __expf(rawv);
    __syncthreads();
    float rsc = 1.0f;
    if (RN) {
        const float w0 = buf[0];
        int ex = (__float_as_int(w0) >> 23) & 0xFF;
        ex = max(1, min(ex, 253));
        e_sum += ex - 127;
        rsc = __int_as_float((254 - ex) << 23);
    }
    float pA, pB;
    dot_rs(buf + hoff, EpA, EpB, pA, pB);
    const float own  = h ? pB : pA;
    const float ship = h ? pA : pB;
    const float recv = __shfl_xor_sync(0xffffffffu, ship, 1);
    const float r = own + recv;
    return RN ? (r * rsc) : r;
}

// ---------------------------------------------------------------------------
// Combine for batch b (one full warp of the last-arriving party).
// ---------------------------------------------------------------------------
__device__ void finish(int b, int lane, float* __restrict__ out, int fast) {
    __threadfence();
    float denom;
    if (fast) {
        float p = g_v[b][lane] * g_u[b][lane]
                + g_v[b][lane + 32] * g_u[b][lane + 32];
#pragma unroll
        for (int o = 16; o > 0; o >>= 1)
            p += __shfl_xor_sync(0xffffffffu, p, o);
        denom = g_m0[b] + (float)(g_esF[b] + g_esB[b]) * LN2 + logf(p);
    } else {
        denom = g_denomG[b];
    }
    const float ll = g_score[b] - denom;
    if (lane == 0) {
        g_tick[b] = 0;
        long long q = llrintf(ll * 65536.0f);
        atomicAdd(&g_acc, (ull)q);
        __threadfence();
        int od = atomicAdd(&g_done, 1);
        if (od == BAT - 1) {
            __threadfence();
            long long a = (long long)atomicAdd(&g_acc, 0ull);
            out[0] = (float)((double)a / 65536.0);
            g_acc = 0ull;
            g_done = 0;
            g_mask_zero = 0;
        }
    }
}

__device__ __forceinline__ void arrive(int b, int lane, float* __restrict__ out,
                                       int fast) {
    const int K = fast ? 3 : 2;
    int last = 0;
    if (lane == 0) {
        int o = atomicAdd(&g_tick[b], 1);
        last = (o == K - 1);
    }
    last = __shfl_sync(0xffffffffu, last, 0);
    if (last) finish(b, lane, out, fast);
}

// ---------------------------------------------------------------------------
// Split kernel, grid = 2*BAT + BAT/2 blocks of 64 threads.
// ---------------------------------------------------------------------------
__global__ void __launch_bounds__(64, 10) crf_split_kernel(
    const float* __restrict__ logits,
    const void*  __restrict__ tags,
    const float* __restrict__ trans,
    const float* __restrict__ startt,
    const float* __restrict__ endt,
    float* __restrict__ out)
{
    const int fast = (g_mask_zero == 0);
    const int bid = blockIdx.x;
    const int tid = threadIdx.x;

    // ========================= score blocks (champion, verbatim) ============
    if (bid >= 2 * BAT) {
        const int w = tid >> 5;
        const int lane = tid & 31;
        const int b = 2 * (bid - 2 * BAT) + w;

        const int probe = ((const int*)tags)[2 * lane + 1];
        const int is64 = (__ballot_sync(0xffffffffu, probe != 0) == 0u);

        float s = 0.f;
        if (fast) {
            for (int t = lane; t < SEQ - 1; t += 32) {
                const int tg = load_tag(tags, (size_t)t * BAT + b, is64);
                const int tgn = load_tag(tags, (size_t)(t + 1) * BAT + b, is64);
                s += trans[tg * NTAG + tgn];
                s += logits[((size_t)t * BAT + b) * NTAG + tg];
            }
#pragma unroll
            for (int o = 16; o > 0; o >>= 1)
                s += __shfl_xor_sync(0xffffffffu, s, o);
            if (lane == 0) {
                const int last_tag = load_tag(tags, (size_t)(SEQ - 1) * BAT + b, is64);
                const int tg0 = load_tag(tags, (size_t)b, is64);
                g_score[b] = s + startt[tg0] + endt[last_tag]
                           + logits[((size_t)(SEQ - 1) * BAT + b) * NTAG + last_tag];
                __threadfence();
            }
            arrive(b, lane, out, fast);
            return;
        }
        const int* mrow = &g_maskT[b * SEQ];
        int msum = 0;
        for (int t = lane; t < SEQ; t += 32) {
            const int tg = load_tag(tags, (size_t)t * BAT + b, is64);
            const int mt = mrow[t];
            msum += mt;
            if (t < SEQ - 1) {
                const int tgn = load_tag(tags, (size_t)(t + 1) * BAT + b, is64);
                const int mtn = mrow[t + 1];
                s += trans[tg * NTAG + tgn] * (float)mtn;
                s += logits[((size_t)t * BAT + b) * NTAG + tg] * (float)mt;
            }
        }
#pragma unroll
        for (int o = 16; o > 0; o >>= 1) {
            s += __shfl_xor_sync(0xffffffffu, s, o);
            msum += __shfl_xor_sync(0xffffffffu, msum, o);
        }
        if (lane == 0) {
            const int last_idx = msum - 1;
            const int last_tag = load_tag(tags, (size_t)last_idx * BAT + b, is64);
            const int tg0 = load_tag(tags, (size_t)b, is64);
            const float mlast = (float)mrow[SEQ - 1];
            g_score[b] = s + startt[tg0] + endt[last_tag]
                       + logits[((size_t)(SEQ - 1) * BAT + b) * NTAG + last_tag] * mlast;
            __threadfence();
        }
        arrive(b, lane, out, fast);
        return;
    }

    // ========================= chain blocks =========================
    const int isBwd = (bid >= BAT);
    const int b = isBwd ? (bid - BAT) : bid;
    const int w = tid >> 5;
    const int l = tid & 31;

    __shared__ __align__(16) float se[2][SE_STR];    // row-split buffers
    __shared__ float aux[4];

    if (!fast) {
        // ---- GENERAL PATH: champion full log-space chain (verbatim) ----
        if (isBwd) return;
        const int j = tid;

        ull Ep[NTAG / 2];
#pragma unroll
        for (int i = 0; i < NTAG / 2; i++) {
            float e0 = __expf(trans[(2 * i) * NTAG + j]);
            float e1 = __expf(trans[(2 * i + 1) * NTAG + j]);
            asm("mov.b64 %0, {%1, %2};" : "=l"(Ep[i]) : "f"(e0), "f"(e1));
        }

        __shared__ __align__(16) float seG[2][NTAG];

        float alpha = startt[j] + logits[(size_t)b * NTAG + j];
        if (j == 0) aux[0] = alpha;
        __syncthreads();
        float m = aux[0];

        const int* mrow = &g_maskT[b * SEQ];
        const float* lptr = logits + (size_t)b * NTAG + j;
        float logit_next = lptr[(size_t)1 * TSTRIDE];

        for (int t = 1; t < SEQ; t++) {
            float* buf = seG[t & 1];
            const float logit = logit_next;
            if (t + 1 < SEQ) logit_next = lptr[(size_t)(t + 1) * TSTRIDE];
            const int mk = mrow[t];

            buf[j] = __expf(alpha - m);
            if (j == 0) aux[1] = alpha;
            __syncthreads();

            const float v = dot64(buf, Ep);
            const float na = logit + m + __logf(v);
            alpha = mk ? na : alpha;
            m = aux[1];
            __syncthreads();
        }

        float x = alpha + endt[j];
        float mm = x;
#pragma unroll
        for (int o = 16; o > 0; o >>= 1)
            mm = fmaxf(mm, __shfl_xor_sync(0xffffffffu, mm, o));
        if (l == 0) aux[w] = mm;
        __syncthreads();
        mm = fmaxf(aux[0], aux[1]);
        float e = __expf(x - mm);
#pragma unroll
        for (int o = 16; o > 0; o >>= 1)
            e += __shfl_xor_sync(0xffffffffu, e, o);
        if (l == 0) aux[2 + w] = e;
        __syncthreads();
        if (j == 0) g_denomG[b] = mm + logf(aux[2] + aux[3]);
        __threadfence();
        __syncthreads();
        if (w == 0) arrive(b, l, out, fast);
        return;
    }

    // ========================= FAST PATH (row-split) =========================
    // Thread pair (2k, 2k+1): even lane h=0 covers rows 0-31, odd h=1 rows
    // 32-63, both for columns (k, k+32). Even finalizes col k, odd col k+32.
    const int h = tid & 1;
    const int k = tid >> 1;
    const int mycol = k + 32 * h;
    const int pos = mycol + ((mycol >> 5) << 4);   // cols 32.. shifted by +16
    const int hoff = 48 * h;                       // row-half base (floats)

    const float* lptr = logits + (size_t)b * NTAG + mycol;

    if (!isBwd) {
        // ---- forward half: 512 steps ----
        // EpA[i] = (E[32h+2i][k], E[32h+2i+1][k]); EpB same for col k+32.
        ull EpA[16], EpB[16];
#pragma unroll
        for (int i = 0; i < 16; i++) {
            const int r = 32 * h + 2 * i;
            float a0 = __expf(trans[r * NTAG + k]);
            float a1 = __expf(trans[(r + 1) * NTAG + k]);
            float b0 = __expf(trans[r * NTAG + k + 32]);
            float b1 = __expf(trans[(r + 1) * NTAG + k + 32]);
            asm("mov.b64 %0, {%1, %2};" : "=l"(EpA[i]) : "f"(a0), "f"(a1));
            asm("mov.b64 %0, {%1, %2};" : "=l"(EpB[i]) : "f"(b0), "f"(b1));
        }

        const float alpha0 = startt[mycol] + lptr[0];
        if (tid == 0) aux[0] = alpha0;
        __syncthreads();
        const float m0 = aux[0];
        float sj = __expf(alpha0 - m0);
        se[0][pos] = sj;

        float raw[4];
#pragma unroll
        for (int u = 0; u < 4; u++)
            raw[u] = lptr[(size_t)(1 + u) * TSTRIDE];
        __syncthreads();   // se[0] visible

        int esF = 0;
        const float* pf = lptr + (size_t)5 * TSTRIDE;
        for (int g = 0; g < 128; g++) {   // t = 1..512; prefetch max t=516 valid
#pragma unroll
            for (int u = 0; u < 4; u++) {
                if (u == 0)
                    sj = fstep_rs<true >(se[u & 1], se[(u & 1) ^ 1], pos, hoff, h,
                                         EpA, EpB, raw[u], esF);
                else
                    sj = fstep_rs<false>(se[u & 1], se[(u & 1) ^ 1], pos, hoff, h,
                                         EpA, EpB, raw[u], esF);
                raw[u] = pf[(size_t)u * TSTRIDE];
            }
            pf += (size_t)4 * TSTRIDE;
        }

        g_v[b][mycol] = sj;
        if (tid == 0) { g_m0[b] = m0; g_esF[b] = esF; }
        __threadfence();
        __syncthreads();
        if (w == 0) arrive(b, l, out, fast);
        return;
    } else {
        // ---- backward half: 511 steps ----
        // EpA[i] = (E[k][32h+2i], E[k][32h+2i+1]); EpB same for row k+32.
        ull EpA[16], EpB[16];
#pragma unroll
        for (int i = 0; i < 16; i++) {
            const int r = 32 * h + 2 * i;
            float a0 = __expf(trans[k * NTAG + r]);
            float a1 = __expf(trans[k * NTAG + r + 1]);
            float b0 = __expf(trans[(k + 32) * NTAG + r]);
            float b1 = __expf(trans[(k + 32) * NTAG + r + 1]);
            asm("mov.b64 %0, {%1, %2};" : "=l"(EpA[i]) : "f"(a0), "f"(a1));
            asm("mov.b64 %0, {%1, %2};" : "=l"(EpB[i]) : "f"(b0), "f"(b1));
        }

        float u_val = __expf(endt[mycol]);

        float raw[4];
#pragma unroll
        for (int u = 0; u < 4; u++)
            raw[u] = lptr[(size_t)(1023 - u) * TSTRIDE];

        int esB = 0;
        const float* pfb = lptr + (size_t)1019 * TSTRIDE;
        for (int g = 0; g < 127; g++) {   // k = 0..507; prefetch min t=512 valid
#pragma unroll
            for (int u = 0; u < 4; u++) {
                if (u == 0)
                    u_val = bstep_rs<true >(se[u & 1], pos, hoff, h,
                                            EpA, EpB, raw[u], u_val, esB);
                else
                    u_val = bstep_rs<false>(se[u & 1], pos, hoff, h,
                                            EpA, EpB, raw[u], u_val, esB);
                raw[u] = pfb[-(long)u * TSTRIDE];
            }
            pfb -= (size_t)4 * TSTRIDE;
        }
#pragma unroll
        for (int u = 0; u < 3; u++) {     // k = 508..510
            if (u == 0)
                u_val = bstep_rs<true >(se[u & 1], pos, hoff, h,
                                        EpA, EpB, raw[u], u_val, esB);
            else
                u_val = bstep_rs<false>(se[u & 1], pos, hoff, h,
                                        EpA, EpB, raw[u], u_val, esB);
        }

        g_u[b][mycol] = u_val;
        if (tid == 0) g_esB[b] = esB;
        __threadfence();
        __syncthreads();
        if (w == 0) arrive(b, l, out, fast);
        return;
    }
}

// ---------------------------------------------------------------------------
extern "C" void kernel_launch(void* const* d_in, const int* in_sizes, int n_in,
                              void* d_out, int out_size) {
    const float* logits = (const float*)d_in[0];
    const void*  tags   = d_in[1];
    const int*   mask   = (const int*)d_in[2];
    const float* trans  = (const float*)d_in[3];
    const float* startt = (const float*)d_in[4];
    const float* endt   = (const float*)d_in[5];
    float* out = (float*)d_out;

    mask_transpose_kernel<<<(SEQ * BAT + 255) / 256, 256>>>(mask);
    crf_split_kernel<<<2 * BAT + BAT / 2, 64>>>(logits, tags, trans,
                                                startt, endt, out);
}